// round 3
// baseline (speedup 1.0000x reference)
#include <cuda_runtime.h>
#include <math.h>

// Problem constants
#define N_PTS   8192
#define H_DIM   512
#define D_DIM   256
#define G_GRP   64
#define M_TOT   16384   // za and zb stacked

// Device scratch (allocation-free rule: static __device__ arrays)
__device__ float g_B0[M_TOT * H_DIM];     // 32 MB
__device__ float g_B1[M_TOT * H_DIM];     // 32 MB
__device__ float g_P [M_TOT * D_DIM];     // 16 MB  (za_p rows 0..8191, zb_p rows 8192..16383)
__device__ float g_norm2[M_TOT];
__device__ float g_invn [M_TOT];
__device__ float g_rowsum[N_PTS];
__device__ float g_colsum[N_PTS];
__device__ float g_rdot  [N_PTS];
__device__ float g_cdot  [N_PTS];
__device__ float g_psg [G_GRP];
__device__ float g_bsim[G_GRP * G_GRP];

// ---------------------------------------------------------------------------
__global__ void init_kernel() {
    int i = blockIdx.x * blockDim.x + threadIdx.x;
    int stride = gridDim.x * blockDim.x;
    for (int j = i; j < M_TOT; j += stride) g_norm2[j] = 0.f;
    for (int j = i; j < N_PTS; j += stride) {
        g_rowsum[j] = 0.f; g_colsum[j] = 0.f; g_rdot[j] = 0.f; g_cdot[j] = 0.f;
    }
    for (int j = i; j < G_GRP * G_GRP; j += stride) g_bsim[j] = 0.f;
    for (int j = i; j < G_GRP; j += stride) g_psg[j] = 0.f;
}

// ---------------------------------------------------------------------------
// GEMM + DyT epilogue:  Y = tanh(a * (X@W + b)) * gamma + beta
// X: [M, K] (optionally split into Xa rows<8192 / Xb rows>=8192), W: [K, N]
// 128x128 tile, 8x8 microtile, 256 threads, BK=8, double-buffered smem.
__global__ __launch_bounds__(256)
void gemm_dyt_kernel(const float* __restrict__ Xa, const float* __restrict__ Xb,
                     const float* __restrict__ W,  const float* __restrict__ bias,
                     const float* __restrict__ alpha, const float* __restrict__ gam,
                     const float* __restrict__ bet, float* __restrict__ Y,
                     int K, int N)
{
    __shared__ float As[2][8][128];
    __shared__ float Bs[2][8][128];

    const int tid = threadIdx.x;
    const int tx = tid & 15, ty = tid >> 4;
    const int rowBase = blockIdx.y * 128;
    const int colBase = blockIdx.x * 128;

    const float* X = (Xb != nullptr && rowBase >= N_PTS)
                       ? (Xb + (size_t)(rowBase - N_PTS) * K)
                       : (Xa + (size_t)rowBase * K);

    const int arow = tid >> 1, ak4 = (tid & 1) * 4;
    const int bk = tid >> 5, bcol4 = (tid & 31) * 4;

    float acc[8][8];
    #pragma unroll
    for (int r = 0; r < 8; r++)
        #pragma unroll
        for (int c = 0; c < 8; c++) acc[r][c] = 0.f;

    const int NITER = K / 8;

    // prologue: fill buffer 0
    {
        float4 av = *(const float4*)&X[(size_t)arow * K + ak4];
        float4 bv = *(const float4*)&W[(size_t)bk * N + colBase + bcol4];
        As[0][ak4 + 0][arow] = av.x; As[0][ak4 + 1][arow] = av.y;
        As[0][ak4 + 2][arow] = av.z; As[0][ak4 + 3][arow] = av.w;
        *(float4*)&Bs[0][bk][bcol4] = bv;
    }
    __syncthreads();

    for (int it = 0; it < NITER; it++) {
        const int cur = it & 1;
        float4 av2, bv2;
        if (it + 1 < NITER) {
            int k0 = (it + 1) * 8;
            av2 = *(const float4*)&X[(size_t)arow * K + k0 + ak4];
            bv2 = *(const float4*)&W[(size_t)(k0 + bk) * N + colBase + bcol4];
        }
        #pragma unroll
        for (int k = 0; k < 8; k++) {
            float ar[8], br[8];
            *(float4*)&ar[0] = *(const float4*)&As[cur][k][ty * 8];
            *(float4*)&ar[4] = *(const float4*)&As[cur][k][ty * 8 + 4];
            *(float4*)&br[0] = *(const float4*)&Bs[cur][k][tx * 8];
            *(float4*)&br[4] = *(const float4*)&Bs[cur][k][tx * 8 + 4];
            #pragma unroll
            for (int r = 0; r < 8; r++)
                #pragma unroll
                for (int c = 0; c < 8; c++)
                    acc[r][c] = fmaf(ar[r], br[c], acc[r][c]);
        }
        if (it + 1 < NITER) {
            const int nxt = cur ^ 1;
            As[nxt][ak4 + 0][arow] = av2.x; As[nxt][ak4 + 1][arow] = av2.y;
            As[nxt][ak4 + 2][arow] = av2.z; As[nxt][ak4 + 3][arow] = av2.w;
            *(float4*)&Bs[nxt][bk][bcol4] = bv2;
            __syncthreads();
        }
    }

    const float a = alpha[0];
    float gj[8], bj[8], bb[8];
    #pragma unroll
    for (int c = 0; c < 8; c++) {
        int j = colBase + tx * 8 + c;
        gj[c] = gam[j]; bj[c] = bet[j]; bb[c] = bias[j];
    }
    #pragma unroll
    for (int r = 0; r < 8; r++) {
        int i = rowBase + ty * 8 + r;
        float y[8];
        #pragma unroll
        for (int c = 0; c < 8; c++) {
            float h = acc[r][c] + bb[c];
            y[c] = tanhf(a * h) * gj[c] + bj[c];
        }
        *(float4*)&Y[(size_t)i * N + colBase + tx * 8]     = *(float4*)&y[0];
        *(float4*)&Y[(size_t)i * N + colBase + tx * 8 + 4] = *(float4*)&y[4];
    }
}

// ---------------------------------------------------------------------------
// GEMM3 + SiLU epilogue + squared-norm accumulation + output write.
// P = silu(X@W3 + b3);  also writes d_out: [0]=loss, then concat(za_p, zb_p).
__global__ __launch_bounds__(256)
void gemm3_silu_kernel(const float* __restrict__ X, const float* __restrict__ W,
                       const float* __restrict__ bias, float* __restrict__ out)
{
    __shared__ float As[2][8][128];
    __shared__ float Bs[2][8][128];

    const int tid = threadIdx.x;
    const int tx = tid & 15, ty = tid >> 4;
    const int rowBase = blockIdx.y * 128;
    const int colBase = blockIdx.x * 128;
    const int K = H_DIM, N = D_DIM;

    const int arow = tid >> 1, ak4 = (tid & 1) * 4;
    const int bk = tid >> 5, bcol4 = (tid & 31) * 4;

    float acc[8][8];
    #pragma unroll
    for (int r = 0; r < 8; r++)
        #pragma unroll
        for (int c = 0; c < 8; c++) acc[r][c] = 0.f;

    const int NITER = K / 8;

    {
        float4 av = *(const float4*)&X[(size_t)(rowBase + arow) * K + ak4];
        float4 bv = *(const float4*)&W[(size_t)bk * N + colBase + bcol4];
        As[0][ak4 + 0][arow] = av.x; As[0][ak4 + 1][arow] = av.y;
        As[0][ak4 + 2][arow] = av.z; As[0][ak4 + 3][arow] = av.w;
        *(float4*)&Bs[0][bk][bcol4] = bv;
    }
    __syncthreads();

    for (int it = 0; it < NITER; it++) {
        const int cur = it & 1;
        float4 av2, bv2;
        if (it + 1 < NITER) {
            int k0 = (it + 1) * 8;
            av2 = *(const float4*)&X[(size_t)(rowBase + arow) * K + k0 + ak4];
            bv2 = *(const float4*)&W[(size_t)(k0 + bk) * N + colBase + bcol4];
        }
        #pragma unroll
        for (int k = 0; k < 8; k++) {
            float ar[8], br[8];
            *(float4*)&ar[0] = *(const float4*)&As[cur][k][ty * 8];
            *(float4*)&ar[4] = *(const float4*)&As[cur][k][ty * 8 + 4];
            *(float4*)&br[0] = *(const float4*)&Bs[cur][k][tx * 8];
            *(float4*)&br[4] = *(const float4*)&Bs[cur][k][tx * 8 + 4];
            #pragma unroll
            for (int r = 0; r < 8; r++)
                #pragma unroll
                for (int c = 0; c < 8; c++)
                    acc[r][c] = fmaf(ar[r], br[c], acc[r][c]);
        }
        if (it + 1 < NITER) {
            const int nxt = cur ^ 1;
            As[nxt][ak4 + 0][arow] = av2.x; As[nxt][ak4 + 1][arow] = av2.y;
            As[nxt][ak4 + 2][arow] = av2.z; As[nxt][ak4 + 3][arow] = av2.w;
            *(float4*)&Bs[nxt][bk][bcol4] = bv2;
            __syncthreads();
        }
    }

    float bb[8];
    #pragma unroll
    for (int c = 0; c < 8; c++) bb[c] = bias[colBase + tx * 8 + c];

    float nrm[8];
    #pragma unroll
    for (int r = 0; r < 8; r++) nrm[r] = 0.f;

    #pragma unroll
    for (int r = 0; r < 8; r++) {
        int i = rowBase + ty * 8 + r;
        float v[8];
        #pragma unroll
        for (int c = 0; c < 8; c++) {
            float p = acc[r][c] + bb[c];
            float s = 1.f / (1.f + __expf(-p));
            v[c] = p * s;
            nrm[r] += v[c] * v[c];
        }
        int jb = colBase + tx * 8;
        *(float4*)&g_P[(size_t)i * N + jb]     = *(float4*)&v[0];
        *(float4*)&g_P[(size_t)i * N + jb + 4] = *(float4*)&v[4];
        // d_out: [0]=loss, then concat(za_p, zb_p) row-major [8192, 512].
        // Base offset is +1 float => 16B-misaligned; MUST use scalar stores.
        size_t orow = (i < N_PTS) ? (size_t)i : (size_t)(i - N_PTS);
        size_t ocol = (i < N_PTS) ? (size_t)jb : (size_t)(jb + D_DIM);
        float* orow_ptr = out + 1 + orow * 512 + ocol;
        #pragma unroll
        for (int c = 0; c < 8; c++) orow_ptr[c] = v[c];
    }

    // reduce nrm across tx (this block covers 128 of the 256 cols)
    __syncthreads();
    __shared__ float red[128 * 16];
    #pragma unroll
    for (int r = 0; r < 8; r++) red[(ty * 8 + r) * 16 + tx] = nrm[r];
    __syncthreads();
    if (tid < 128) {
        float s = 0.f;
        #pragma unroll
        for (int t = 0; t < 16; t++) s += red[tid * 16 + t];
        atomicAdd(&g_norm2[rowBase + tid], s);
    }
}

// ---------------------------------------------------------------------------
__global__ void invnorm_kernel() {
    int i = blockIdx.x * blockDim.x + threadIdx.x;
    if (i < M_TOT) g_invn[i] = rsqrtf(g_norm2[i]);
}

// ---------------------------------------------------------------------------
// Fused similarity GEMM + all reductions. m is never materialized in HBM.
// Tile (bi, bj): rows I = za_p[I0..I0+127], cols J = zb_p[J0..J0+127].
//   m[i][j] = exp( dot(za_p[i], zb_p[j]) * invn_a[i] * invn_b[j] * (1/TAU) )
// Accumulates: rowsum[i], colsum[j], rdot[i] (+=m*pos[i,j]), cdot[j] (+=m*pos[j,i]),
// batch_sim[g(I), g(J)] (tile sum), psg[g] (diag when bi==bj).
// Double-buffered smem mainloop; buffers reused for the reduction passes.
__global__ __launch_bounds__(256)
void sim_reduce_kernel(const float* __restrict__ pos, const int* __restrict__ batch)
{
    __shared__ float smem[4096];   // 2 x (As(8x128) | Bs(8x128))
    #define AS(b, k, i) smem[(b) * 2048 + (k) * 128 + (i)]
    #define BS(b, k, j) smem[(b) * 2048 + 1024 + (k) * 128 + (j)]

    const int tid = threadIdx.x;
    const int tx = tid & 15, ty = tid >> 4;
    const int bi = blockIdx.y, bj = blockIdx.x;
    const int I0 = bi * 128, J0 = bj * 128;
    const int K = D_DIM;

    const float* A = g_P + (size_t)I0 * K;
    const float* B = g_P + (size_t)(N_PTS + J0) * K;

    const int arow = tid >> 1, ak4 = (tid & 1) * 4;

    float acc[8][8];
    #pragma unroll
    for (int r = 0; r < 8; r++)
        #pragma unroll
        for (int c = 0; c < 8; c++) acc[r][c] = 0.f;

    const int NITER = K / 8;

    {
        float4 av = *(const float4*)&A[(size_t)arow * K + ak4];
        float4 bv = *(const float4*)&B[(size_t)arow * K + ak4];
        AS(0, ak4 + 0, arow) = av.x; AS(0, ak4 + 1, arow) = av.y;
        AS(0, ak4 + 2, arow) = av.z; AS(0, ak4 + 3, arow) = av.w;
        BS(0, ak4 + 0, arow) = bv.x; BS(0, ak4 + 1, arow) = bv.y;
        BS(0, ak4 + 2, arow) = bv.z; BS(0, ak4 + 3, arow) = bv.w;
    }
    __syncthreads();

    for (int it = 0; it < NITER; it++) {
        const int cur = it & 1;
        float4 av2, bv2;
        if (it + 1 < NITER) {
            int k0 = (it + 1) * 8;
            av2 = *(const float4*)&A[(size_t)arow * K + k0 + ak4];
            bv2 = *(const float4*)&B[(size_t)arow * K + k0 + ak4];
        }
        #pragma unroll
        for (int k = 0; k < 8; k++) {
            float ar[8], br[8];
            *(float4*)&ar[0] = *(const float4*)&AS(cur, k, ty * 8);
            *(float4*)&ar[4] = *(const float4*)&AS(cur, k, ty * 8 + 4);
            *(float4*)&br[0] = *(const float4*)&BS(cur, k, tx * 8);
            *(float4*)&br[4] = *(const float4*)&BS(cur, k, tx * 8 + 4);
            #pragma unroll
            for (int r = 0; r < 8; r++)
                #pragma unroll
                for (int c = 0; c < 8; c++)
                    acc[r][c] = fmaf(ar[r], br[c], acc[r][c]);
        }
        if (it + 1 < NITER) {
            const int nxt = cur ^ 1;
            AS(nxt, ak4 + 0, arow) = av2.x; AS(nxt, ak4 + 1, arow) = av2.y;
            AS(nxt, ak4 + 2, arow) = av2.z; AS(nxt, ak4 + 3, arow) = av2.w;
            BS(nxt, ak4 + 0, arow) = bv2.x; BS(nxt, ak4 + 1, arow) = bv2.y;
            BS(nxt, ak4 + 2, arow) = bv2.z; BS(nxt, ak4 + 3, arow) = bv2.w;
            __syncthreads();
        }
    }

    // normalize + exp (1/TAU = 2), accumulate rs/cs/rd in one pass over pos[i,:]
    float inA[8], inB[8];
    #pragma unroll
    for (int r = 0; r < 8; r++) inA[r] = g_invn[I0 + ty * 8 + r];
    #pragma unroll
    for (int c = 0; c < 8; c++) inB[c] = g_invn[N_PTS + J0 + tx * 8 + c];

    float rs[8], cs[8], rd[8], cd[8];
    #pragma unroll
    for (int r = 0; r < 8; r++) { rs[r] = 0.f; rd[r] = 0.f; }
    #pragma unroll
    for (int c = 0; c < 8; c++) { cs[c] = 0.f; cd[c] = 0.f; }

    #pragma unroll
    for (int r = 0; r < 8; r++) {
        size_t i = (size_t)(I0 + ty * 8 + r);
        float pa[8];
        *(float4*)&pa[0] = *(const float4*)&pos[i * N_PTS + J0 + tx * 8];
        *(float4*)&pa[4] = *(const float4*)&pos[i * N_PTS + J0 + tx * 8 + 4];
        #pragma unroll
        for (int c = 0; c < 8; c++) {
            float mm = __expf(acc[r][c] * inA[r] * inB[c] * 2.0f);
            acc[r][c] = mm;
            rs[r] += mm;
            cs[c] += mm;
            rd[r] += mm * pa[c];
        }
    }
    // cdot[j] += m[i][j] * pos[j, i]  (pos rows j, i contiguous -> clean loads)
    #pragma unroll
    for (int c = 0; c < 8; c++) {
        size_t j = (size_t)(J0 + tx * 8 + c);
        float pb[8];
        *(float4*)&pb[0] = *(const float4*)&pos[j * N_PTS + I0 + ty * 8];
        *(float4*)&pb[4] = *(const float4*)&pos[j * N_PTS + I0 + ty * 8 + 4];
        #pragma unroll
        for (int r = 0; r < 8; r++)
            cd[c] += acc[r][c] * pb[r];
    }

    const int gI = batch[I0];
    const int gJ = batch[J0];

    // diag (i==j requires bi==bj, tx==ty, r==c)
    if (bi == bj && tx == ty) {
        float d = 0.f;
        #pragma unroll
        for (int r = 0; r < 8; r++) d += acc[r][r];
        atomicAdd(&g_psg[gI], d);
    }

    // --- reduction passes through smem (reuse buffer space) ---
    // pass 1: rowsum + tile total
    __syncthreads();
    #pragma unroll
    for (int r = 0; r < 8; r++) smem[(ty * 8 + r) * 16 + tx] = rs[r];
    __syncthreads();
    float rowtot = 0.f;
    if (tid < 128) {
        #pragma unroll
        for (int t = 0; t < 16; t++) rowtot += smem[tid * 16 + t];
        atomicAdd(&g_rowsum[I0 + tid], rowtot);
    }
    __syncthreads();
    if (tid < 128) smem[tid] = rowtot;
    __syncthreads();
    if (tid < 32) {
        float s = smem[tid] + smem[tid + 32] + smem[tid + 64] + smem[tid + 96];
        #pragma unroll
        for (int o = 16; o > 0; o >>= 1) s += __shfl_down_sync(0xffffffffu, s, o);
        if (tid == 0) atomicAdd(&g_bsim[gI * G_GRP + gJ], s);
    }

    // pass 2: rdot
    __syncthreads();
    #pragma unroll
    for (int r = 0; r < 8; r++) smem[(ty * 8 + r) * 16 + tx] = rd[r];
    __syncthreads();
    if (tid < 128) {
        float s = 0.f;
        #pragma unroll
        for (int t = 0; t < 16; t++) s += smem[tid * 16 + t];
        atomicAdd(&g_rdot[I0 + tid], s);
    }

    // pass 3: colsum
    __syncthreads();
    #pragma unroll
    for (int c = 0; c < 8; c++) smem[(tx * 8 + c) * 16 + ty] = cs[c];
    __syncthreads();
    if (tid < 128) {
        float s = 0.f;
        #pragma unroll
        for (int t = 0; t < 16; t++) s += smem[tid * 16 + t];
        atomicAdd(&g_colsum[J0 + tid], s);
    }

    // pass 4: cdot
    __syncthreads();
    #pragma unroll
    for (int c = 0; c < 8; c++) smem[(tx * 8 + c) * 16 + ty] = cd[c];
    __syncthreads();
    if (tid < 128) {
        float s = 0.f;
        #pragma unroll
        for (int t = 0; t < 16; t++) s += smem[tid * 16 + t];
        atomicAdd(&g_cdot[J0 + tid], s);
    }
    #undef AS
    #undef BS
}

// ---------------------------------------------------------------------------
__device__ __forceinline__ float block_reduce_256(float v, float* sh) {
    int tid = threadIdx.x;
    sh[tid] = v;
    __syncthreads();
    for (int s = 128; s > 0; s >>= 1) {
        if (tid < s) sh[tid] += sh[tid + s];
        __syncthreads();
    }
    float r = sh[0];
    __syncthreads();
    return r;
}

__global__ __launch_bounds__(256)
void finalize_kernel(float* __restrict__ out)
{
    __shared__ float sh[256];
    const int tid = threadIdx.x;
    const float EPS_G = 1e-6f, EPS_L = 1e-5f;

    float sa = 0.f, sb = 0.f;
    for (int i = tid; i < N_PTS; i += 256) {
        sa += logf(g_rdot[i] / (g_rowsum[i] + EPS_G));
        sb += logf(g_cdot[i] / (g_colsum[i] + EPS_G));
    }
    sa = block_reduce_256(sa, sh);
    sb = block_reduce_256(sb, sh);
    float global_loss = 0.5f * (-sa / (float)N_PTS) + 0.5f * (-sb / (float)N_PTS);

    float l0 = 0.f, l1 = 0.f, inn = 0.f;
    if (tid < G_GRP) {
        int g = tid;
        float gs = g_bsim[g * G_GRP + g];
        float rsum = 0.f, csum = 0.f;
        for (int h = 0; h < G_GRP; h++) {
            rsum += g_bsim[g * G_GRP + h];
            csum += g_bsim[h * G_GRP + g];
        }
        float neg1 = rsum - gs;
        float neg0 = csum - gs;
        float p = g_psg[g];
        l0  = logf(p / (neg0 + EPS_L));
        l1  = logf(p / (neg1 + EPS_L));
        inn = logf(p / (gs - p + EPS_L));
    }
    l0  = block_reduce_256(l0,  sh);
    l1  = block_reduce_256(l1,  sh);
    inn = block_reduce_256(inn, sh);

    if (tid == 0) {
        float loss0 = l0 / (float)G_GRP;
        float loss1 = l1 / (float)G_GRP;
        float inter = 0.5f * (loss0 + loss1);
        float inner = -(inn / (float)G_GRP);
        out[0] = global_loss + inter + inner;   // ALPHA = BETA = 1
    }
}

// ---------------------------------------------------------------------------
extern "C" void kernel_launch(void* const* d_in, const int* in_sizes, int n_in,
                              void* d_out, int out_size)
{
    const float* za   = (const float*)d_in[0];
    const float* zb   = (const float*)d_in[1];
    const float* pos  = (const float*)d_in[2];
    const int*   batch = (const int*)d_in[3];
    const float* W1 = (const float*)d_in[4];
    const float* b1 = (const float*)d_in[5];
    const float* a1 = (const float*)d_in[6];
    const float* g1 = (const float*)d_in[7];
    const float* be1 = (const float*)d_in[8];
    const float* W2 = (const float*)d_in[9];
    const float* b2 = (const float*)d_in[10];
    const float* a2 = (const float*)d_in[11];
    const float* g2 = (const float*)d_in[12];
    const float* be2 = (const float*)d_in[13];
    const float* W3 = (const float*)d_in[14];
    const float* b3 = (const float*)d_in[15];
    float* out = (float*)d_out;

    float* B0 = nullptr; float* B1 = nullptr;
    cudaGetSymbolAddress((void**)&B0, g_B0);
    cudaGetSymbolAddress((void**)&B1, g_B1);

    init_kernel<<<64, 256>>>();

    // MLP layer 1: [za; zb] @ W1 -> DyT -> B0
    gemm_dyt_kernel<<<dim3(4, 128), 256>>>(za, zb, W1, b1, a1, g1, be1, B0, H_DIM, H_DIM);
    // MLP layer 2: B0 @ W2 -> DyT -> B1
    gemm_dyt_kernel<<<dim3(4, 128), 256>>>(B0, nullptr, W2, b2, a2, g2, be2, B1, H_DIM, H_DIM);
    // MLP layer 3 + SiLU + norms + output projection write
    gemm3_silu_kernel<<<dim3(2, 128), 256>>>(B1, W3, b3, out);

    invnorm_kernel<<<(M_TOT + 255) / 256, 256>>>();

    // Fused similarity + all contrast reductions
    sim_reduce_kernel<<<dim3(64, 64), 256>>>(pos, batch);

    finalize_kernel<<<1, 256>>>(out);
}

// round 11
// speedup vs baseline: 1.6333x; 1.6333x over previous
#include <cuda_runtime.h>
#include <cuda_bf16.h>
#include <math.h>
#include <stdint.h>

// Problem constants
#define N_PTS   8192
#define H_DIM   512
#define D_DIM   256
#define G_GRP   64
#define M_TOT   16384   // za and zb stacked

// Device scratch (allocation-free rule: static __device__ arrays)
__device__ float g_B0[M_TOT * H_DIM];            // 32 MB
__device__ float g_B1[M_TOT * H_DIM];            // 32 MB
__device__ __nv_bfloat16 g_Pbf[M_TOT * D_DIM];   // 8 MB bf16 shadow of projections
__device__ float g_norm2[M_TOT];
__device__ float g_invn [M_TOT];
__device__ float g_rowsum[N_PTS];
__device__ float g_colsum[N_PTS];
__device__ float g_rdot  [N_PTS];
__device__ float g_cdot  [N_PTS];
__device__ float g_psg [G_GRP];
__device__ float g_bsim[G_GRP * G_GRP];

// ---------------------------------------------------------------------------
// Helpers (sm_103 base target ONLY — no arch-suffix-gated features)
// ---------------------------------------------------------------------------
__device__ __forceinline__ uint32_t smem_u32(const void* p) {
    uint32_t a;
    asm("{ .reg .u64 t; cvta.to.shared.u64 t, %1; cvt.u32.u64 %0, t; }"
        : "=r"(a) : "l"(p));
    return a;
}

__device__ __forceinline__ void ldsm_x4(uint32_t* r, uint32_t addr) {
    asm volatile("ldmatrix.sync.aligned.m8n8.x4.shared.b16 {%0,%1,%2,%3}, [%4];"
                 : "=r"(r[0]), "=r"(r[1]), "=r"(r[2]), "=r"(r[3]) : "r"(addr));
}

__device__ __forceinline__ void mma_bf16(float* d, const uint32_t* a, const uint32_t* b) {
    asm volatile(
        "mma.sync.aligned.m16n8k16.row.col.f32.bf16.bf16.f32 "
        "{%0,%1,%2,%3}, {%4,%5,%6,%7}, {%8,%9}, {%0,%1,%2,%3};"
        : "+f"(d[0]), "+f"(d[1]), "+f"(d[2]), "+f"(d[3])
        : "r"(a[0]), "r"(a[1]), "r"(a[2]), "r"(a[3]), "r"(b[0]), "r"(b[1]));
}

// ---------------------------------------------------------------------------
__global__ void init_kernel() {
    int i = blockIdx.x * blockDim.x + threadIdx.x;
    int stride = gridDim.x * blockDim.x;
    for (int j = i; j < M_TOT; j += stride) g_norm2[j] = 0.f;
    for (int j = i; j < N_PTS; j += stride) {
        g_rowsum[j] = 0.f; g_colsum[j] = 0.f; g_rdot[j] = 0.f; g_cdot[j] = 0.f;
    }
    for (int j = i; j < G_GRP * G_GRP; j += stride) g_bsim[j] = 0.f;
    for (int j = i; j < G_GRP; j += stride) g_psg[j] = 0.f;
}

// ---------------------------------------------------------------------------
// GEMM + DyT epilogue (fp32, double-buffered) — unchanged from passing R3.
__global__ __launch_bounds__(256)
void gemm_dyt_kernel(const float* __restrict__ Xa, const float* __restrict__ Xb,
                     const float* __restrict__ W,  const float* __restrict__ bias,
                     const float* __restrict__ alpha, const float* __restrict__ gam,
                     const float* __restrict__ bet, float* __restrict__ Y,
                     int K, int N)
{
    __shared__ float As[2][8][128];
    __shared__ float Bs[2][8][128];

    const int tid = threadIdx.x;
    const int tx = tid & 15, ty = tid >> 4;
    const int rowBase = blockIdx.y * 128;
    const int colBase = blockIdx.x * 128;

    const float* X = (Xb != nullptr && rowBase >= N_PTS)
                       ? (Xb + (size_t)(rowBase - N_PTS) * K)
                       : (Xa + (size_t)rowBase * K);

    const int arow = tid >> 1, ak4 = (tid & 1) * 4;
    const int bk = tid >> 5, bcol4 = (tid & 31) * 4;

    float acc[8][8];
    #pragma unroll
    for (int r = 0; r < 8; r++)
        #pragma unroll
        for (int c = 0; c < 8; c++) acc[r][c] = 0.f;

    const int NITER = K / 8;

    {
        float4 av = *(const float4*)&X[(size_t)arow * K + ak4];
        float4 bv = *(const float4*)&W[(size_t)bk * N + colBase + bcol4];
        As[0][ak4 + 0][arow] = av.x; As[0][ak4 + 1][arow] = av.y;
        As[0][ak4 + 2][arow] = av.z; As[0][ak4 + 3][arow] = av.w;
        *(float4*)&Bs[0][bk][bcol4] = bv;
    }
    __syncthreads();

    for (int it = 0; it < NITER; it++) {
        const int cur = it & 1;
        float4 av2, bv2;
        if (it + 1 < NITER) {
            int k0 = (it + 1) * 8;
            av2 = *(const float4*)&X[(size_t)arow * K + k0 + ak4];
            bv2 = *(const float4*)&W[(size_t)(k0 + bk) * N + colBase + bcol4];
        }
        #pragma unroll
        for (int k = 0; k < 8; k++) {
            float ar[8], br[8];
            *(float4*)&ar[0] = *(const float4*)&As[cur][k][ty * 8];
            *(float4*)&ar[4] = *(const float4*)&As[cur][k][ty * 8 + 4];
            *(float4*)&br[0] = *(const float4*)&Bs[cur][k][tx * 8];
            *(float4*)&br[4] = *(const float4*)&Bs[cur][k][tx * 8 + 4];
            #pragma unroll
            for (int r = 0; r < 8; r++)
                #pragma unroll
                for (int c = 0; c < 8; c++)
                    acc[r][c] = fmaf(ar[r], br[c], acc[r][c]);
        }
        if (it + 1 < NITER) {
            const int nxt = cur ^ 1;
            As[nxt][ak4 + 0][arow] = av2.x; As[nxt][ak4 + 1][arow] = av2.y;
            As[nxt][ak4 + 2][arow] = av2.z; As[nxt][ak4 + 3][arow] = av2.w;
            *(float4*)&Bs[nxt][bk][bcol4] = bv2;
            __syncthreads();
        }
    }

    const float a = alpha[0];
    float gj[8], bj[8], bb[8];
    #pragma unroll
    for (int c = 0; c < 8; c++) {
        int j = colBase + tx * 8 + c;
        gj[c] = gam[j]; bj[c] = bet[j]; bb[c] = bias[j];
    }
    #pragma unroll
    for (int r = 0; r < 8; r++) {
        int i = rowBase + ty * 8 + r;
        float y[8];
        #pragma unroll
        for (int c = 0; c < 8; c++) {
            float h = acc[r][c] + bb[c];
            y[c] = tanhf(a * h) * gj[c] + bj[c];
        }
        *(float4*)&Y[(size_t)i * N + colBase + tx * 8]     = *(float4*)&y[0];
        *(float4*)&Y[(size_t)i * N + colBase + tx * 8 + 4] = *(float4*)&y[4];
    }
}

// ---------------------------------------------------------------------------
// GEMM3 + SiLU + norms + fp32 d_out write + bf16 shadow write.
__global__ __launch_bounds__(256)
void gemm3_silu_kernel(const float* __restrict__ X, const float* __restrict__ W,
                       const float* __restrict__ bias, float* __restrict__ out)
{
    __shared__ float As[2][8][128];
    __shared__ float Bs[2][8][128];

    const int tid = threadIdx.x;
    const int tx = tid & 15, ty = tid >> 4;
    const int rowBase = blockIdx.y * 128;
    const int colBase = blockIdx.x * 128;
    const int K = H_DIM, N = D_DIM;

    const int arow = tid >> 1, ak4 = (tid & 1) * 4;
    const int bk = tid >> 5, bcol4 = (tid & 31) * 4;

    float acc[8][8];
    #pragma unroll
    for (int r = 0; r < 8; r++)
        #pragma unroll
        for (int c = 0; c < 8; c++) acc[r][c] = 0.f;

    const int NITER = K / 8;

    {
        float4 av = *(const float4*)&X[(size_t)(rowBase + arow) * K + ak4];
        float4 bv = *(const float4*)&W[(size_t)bk * N + colBase + bcol4];
        As[0][ak4 + 0][arow] = av.x; As[0][ak4 + 1][arow] = av.y;
        As[0][ak4 + 2][arow] = av.z; As[0][ak4 + 3][arow] = av.w;
        *(float4*)&Bs[0][bk][bcol4] = bv;
    }
    __syncthreads();

    for (int it = 0; it < NITER; it++) {
        const int cur = it & 1;
        float4 av2, bv2;
        if (it + 1 < NITER) {
            int k0 = (it + 1) * 8;
            av2 = *(const float4*)&X[(size_t)(rowBase + arow) * K + k0 + ak4];
            bv2 = *(const float4*)&W[(size_t)(k0 + bk) * N + colBase + bcol4];
        }
        #pragma unroll
        for (int k = 0; k < 8; k++) {
            float ar[8], br[8];
            *(float4*)&ar[0] = *(const float4*)&As[cur][k][ty * 8];
            *(float4*)&ar[4] = *(const float4*)&As[cur][k][ty * 8 + 4];
            *(float4*)&br[0] = *(const float4*)&Bs[cur][k][tx * 8];
            *(float4*)&br[4] = *(const float4*)&Bs[cur][k][tx * 8 + 4];
            #pragma unroll
            for (int r = 0; r < 8; r++)
                #pragma unroll
                for (int c = 0; c < 8; c++)
                    acc[r][c] = fmaf(ar[r], br[c], acc[r][c]);
        }
        if (it + 1 < NITER) {
            const int nxt = cur ^ 1;
            As[nxt][ak4 + 0][arow] = av2.x; As[nxt][ak4 + 1][arow] = av2.y;
            As[nxt][ak4 + 2][arow] = av2.z; As[nxt][ak4 + 3][arow] = av2.w;
            *(float4*)&Bs[nxt][bk][bcol4] = bv2;
            __syncthreads();
        }
    }

    float bb[8];
    #pragma unroll
    for (int c = 0; c < 8; c++) bb[c] = bias[colBase + tx * 8 + c];

    float nrm[8];
    #pragma unroll
    for (int r = 0; r < 8; r++) nrm[r] = 0.f;

    #pragma unroll
    for (int r = 0; r < 8; r++) {
        int i = rowBase + ty * 8 + r;
        float v[8];
        #pragma unroll
        for (int c = 0; c < 8; c++) {
            float p = acc[r][c] + bb[c];
            float s = 1.f / (1.f + __expf(-p));
            v[c] = p * s;
            nrm[r] += v[c] * v[c];
        }
        int jb = colBase + tx * 8;
        // bf16 shadow for the tensor-core similarity GEMM
        __nv_bfloat162 h2[4];
        #pragma unroll
        for (int q = 0; q < 4; q++)
            h2[q] = __floats2bfloat162_rn(v[2 * q], v[2 * q + 1]);
        *(uint4*)&g_Pbf[(size_t)i * N + jb] = *(uint4*)h2;
        // d_out: [0]=loss, then concat(za_p, zb_p) row-major [8192, 512].
        // Base offset is +1 float => 16B-misaligned; MUST use scalar stores.
        size_t orow = (i < N_PTS) ? (size_t)i : (size_t)(i - N_PTS);
        size_t ocol = (i < N_PTS) ? (size_t)jb : (size_t)(jb + D_DIM);
        float* orow_ptr = out + 1 + orow * 512 + ocol;
        #pragma unroll
        for (int c = 0; c < 8; c++) orow_ptr[c] = v[c];
    }

    __syncthreads();
    __shared__ float red[128 * 16];
    #pragma unroll
    for (int r = 0; r < 8; r++) red[(ty * 8 + r) * 16 + tx] = nrm[r];
    __syncthreads();
    if (tid < 128) {
        float s = 0.f;
        #pragma unroll
        for (int t = 0; t < 16; t++) s += red[tid * 16 + t];
        atomicAdd(&g_norm2[rowBase + tid], s);
    }
}

// ---------------------------------------------------------------------------
__global__ void invnorm_kernel() {
    int i = blockIdx.x * blockDim.x + threadIdx.x;
    if (i < M_TOT) g_invn[i] = rsqrtf(g_norm2[i]);
}

// ---------------------------------------------------------------------------
// mma.sync (bf16 HMMA) similarity GEMM + fused reductions. 256 threads.
// Tile (bi, bj) 128x128, K=256. Operands in smem, rows padded to 528B
// (33 x 16B -> conflict-free ldmatrix). 8 warps in a 4x2 (rowgrp x colgrp)
// grid; warp computes 32x64 via 2x8 m16n8k16 mma tiles, K-loop of 16.
// Raw dot products staged col-major (stride 131) into smem overlay, then the
// proven two-half epilogue (exp, rowsum/rdot/diag, colsum/cdot) runs on it.
#define A_ROW_B   528                  // smem row stride in bytes (264 bf16)
#define SM_A      0
#define SM_B      67584                // 128*528
#define MS_STRIDE 131                  // floats; col-major m buffer
// epilogue float offsets (beyond 135168B operand region)
#define EP_INVB   33792
#define EP_CS     33920                // 2*128
#define EP_CD     34176                // 2*128
#define EP_RED    34432                // 256
#define SIM_SMEM_TOTAL 138752

__global__ __launch_bounds__(256)
void sim_mma_kernel(const float* __restrict__ pos, const int* __restrict__ batch)
{
    extern __shared__ __align__(16) char smem[];
    const uint32_t sb = smem_u32(smem);
    const int tid  = threadIdx.x;
    const int lane = tid & 31;
    const int warp = tid >> 5;
    const int rg = warp >> 1;          // row group: rows rg*32..+31
    const int cg = warp & 1;           // col group: cols cg*64..+63
    const int bi = blockIdx.y, bj = blockIdx.x;
    const int I0 = bi * 128, J0 = bj * 128;

    // ---- load operand tiles (bf16, K-major, padded rows) ----
    const __nv_bfloat16* Abf = g_Pbf + (size_t)I0 * D_DIM;
    const __nv_bfloat16* Bbf = g_Pbf + (size_t)(N_PTS + J0) * D_DIM;
    #pragma unroll
    for (int c = tid; c < 4096; c += 256) {
        int row = c >> 5;              // 0..127
        int kc  = c & 31;              // 16B chunk (8 bf16)
        *(uint4*)(smem + SM_A + row * A_ROW_B + kc * 16) =
            *(const uint4*)&Abf[(size_t)row * D_DIM + kc * 8];
        *(uint4*)(smem + SM_B + row * A_ROW_B + kc * 16) =
            *(const uint4*)&Bbf[(size_t)row * D_DIM + kc * 8];
    }
    __syncthreads();

    // ---- MMA mainloop ----
    float d[2][8][4];
    #pragma unroll
    for (int mt = 0; mt < 2; mt++)
        #pragma unroll
        for (int nt = 0; nt < 8; nt++)
            #pragma unroll
            for (int q = 0; q < 4; q++) d[mt][nt][q] = 0.f;

    // A frag addr: lane 0-15 -> row (lane), k-half 0; lane 16-31 -> row, k+16B
    const uint32_t aBase = sb + SM_A
        + (uint32_t)(rg * 32 + (lane & 15)) * A_ROW_B + ((lane >> 4) * 16);
    // B pair addr: lanes {0-7,8-15,16-23,24-31} -> {n,k0},{n,k+16B},{n+8,k0},{n+8,k+16B}
    const uint32_t bBase = sb + SM_B
        + (uint32_t)(cg * 64 + ((lane >> 4) << 3) + (lane & 7)) * A_ROW_B
        + (((lane >> 3) & 1) * 16);

    #pragma unroll 4
    for (int ks = 0; ks < 16; ks++) {
        const uint32_t koff = (uint32_t)ks * 32;   // 16 bf16 = 32B
        uint32_t a[2][4];
        ldsm_x4(a[0], aBase + koff);
        ldsm_x4(a[1], aBase + 16 * A_ROW_B + koff);
        uint32_t b[8][2];
        #pragma unroll
        for (int np = 0; np < 4; np++) {
            uint32_t t[4];
            ldsm_x4(t, bBase + (uint32_t)np * 16 * A_ROW_B + koff);
            b[2 * np][0] = t[0]; b[2 * np][1] = t[1];
            b[2 * np + 1][0] = t[2]; b[2 * np + 1][1] = t[3];
        }
        #pragma unroll
        for (int mt = 0; mt < 2; mt++)
            #pragma unroll
            for (int nt = 0; nt < 8; nt++)
                mma_bf16(d[mt][nt], a[mt], b[nt]);
    }
    __syncthreads();   // operands dead; overlay follows

    // ---- stage raw dots into col-major smem (stride 131) ----
    float* ms = (float*)smem;
    {
        const int gid = lane >> 2, qp = lane & 3;
        #pragma unroll
        for (int mt = 0; mt < 2; mt++) {
            int r1 = rg * 32 + mt * 16 + gid;
            int r2 = r1 + 8;
            #pragma unroll
            for (int nt = 0; nt < 8; nt++) {
                int c0 = cg * 64 + nt * 8 + qp * 2;
                ms[c0 * MS_STRIDE + r1]       = d[mt][nt][0];
                ms[(c0 + 1) * MS_STRIDE + r1] = d[mt][nt][1];
                ms[c0 * MS_STRIDE + r2]       = d[mt][nt][2];
                ms[(c0 + 1) * MS_STRIDE + r2] = d[mt][nt][3];
            }
        }
    }
    float* ep = (float*)smem;
    if (tid < 128) ep[EP_INVB + tid] = g_invn[N_PTS + J0 + tid];
    __syncthreads();

    // ---- epilogue (two halves over column chunks, thread = row) ----
    const int half = tid >> 7;
    const int row  = tid & 127;
    const float inA = g_invn[I0 + row];
    const bool isdiag = (bi == bj);
    float rs = 0.f, rd = 0.f, dsum = 0.f;

    #pragma unroll 1
    for (int ci = 0; ci < 2; ci++) {
        const int cb = half * 2 + ci;          // column chunk 0..3

        const float* prow = pos + (size_t)(I0 + row) * N_PTS + J0 + cb * 32;
        #pragma unroll
        for (int k = 0; k < 32; k += 4) {
            float4 pv = *(const float4*)&prow[k];
            #pragma unroll
            for (int kk = 0; kk < 4; kk++) {
                int k2 = k + kk;
                int col = cb * 32 + k2;
                float dot = ms[col * MS_STRIDE + row];
                float mm = __expf(dot * inA * ep[EP_INVB + col] * 2.0f);
                ms[col * MS_STRIDE + row] = mm;
                rs += mm;
                rd += mm * ((const float*)&pv)[kk];
                if (isdiag && col == row) dsum += mm;
            }
        }
        __syncthreads();

        // column sums: this half's 128 threads -> (col k, row-quarter q)
        {
            int k = row & 31, q = row >> 5;
            int col = cb * 32 + k;
            float csp = 0.f, cdp = 0.f;
            const float* pcol = pos + (size_t)(J0 + col) * N_PTS + I0 + q * 32;
            #pragma unroll
            for (int r = 0; r < 32; r += 4) {
                float4 pv = *(const float4*)&pcol[r];
                #pragma unroll
                for (int rr = 0; rr < 4; rr++) {
                    float mmv = ms[col * MS_STRIDE + q * 32 + r + rr];
                    csp += mmv;
                    cdp += mmv * ((const float*)&pv)[rr];
                }
            }
            ep[EP_CS + half * 128 + q * 32 + k] = csp;
            ep[EP_CD + half * 128 + q * 32 + k] = cdp;
        }
        __syncthreads();
        if (row < 32) {   // one warp per half finalizes its 32 columns
            float cs = ep[EP_CS + half * 128 + row] + ep[EP_CS + half * 128 + 32 + row]
                     + ep[EP_CS + half * 128 + 64 + row] + ep[EP_CS + half * 128 + 96 + row];
            float cd = ep[EP_CD + half * 128 + row] + ep[EP_CD + half * 128 + 32 + row]
                     + ep[EP_CD + half * 128 + 64 + row] + ep[EP_CD + half * 128 + 96 + row];
            atomicAdd(&g_colsum[J0 + cb * 32 + row], cs);
            atomicAdd(&g_cdot  [J0 + cb * 32 + row], cd);
        }
        __syncthreads();
    }

    // each half covers 64 of 128 columns -> partial row sums; atomics combine
    atomicAdd(&g_rowsum[I0 + row], rs);
    atomicAdd(&g_rdot  [I0 + row], rd);

    const int gI = batch[I0];
    const int gJ = batch[J0];

    // tile total -> bsim (reduce rs over all 256 threads)
    ep[EP_RED + tid] = rs;
    __syncthreads();
    if (tid < 32) {
        float s = 0.f;
        #pragma unroll
        for (int t = 0; t < 8; t++) s += ep[EP_RED + t * 32 + tid];
        #pragma unroll
        for (int o = 16; o > 0; o >>= 1) s += __shfl_down_sync(0xffffffffu, s, o);
        if (tid == 0) atomicAdd(&g_bsim[gI * G_GRP + gJ], s);
    }

    if (isdiag) {
        __syncthreads();
        ep[EP_RED + tid] = dsum;
        __syncthreads();
        if (tid < 32) {
            float s = 0.f;
            #pragma unroll
            for (int t = 0; t < 8; t++) s += ep[EP_RED + t * 32 + tid];
            #pragma unroll
            for (int o = 16; o > 0; o >>= 1) s += __shfl_down_sync(0xffffffffu, s, o);
            if (tid == 0) atomicAdd(&g_psg[gI], s);
        }
    }
}

// ---------------------------------------------------------------------------
__device__ __forceinline__ float block_reduce_256(float v, float* sh) {
    int tid = threadIdx.x;
    sh[tid] = v;
    __syncthreads();
    for (int s = 128; s > 0; s >>= 1) {
        if (tid < s) sh[tid] += sh[tid + s];
        __syncthreads();
    }
    float r = sh[0];
    __syncthreads();
    return r;
}

__global__ __launch_bounds__(256)
void finalize_kernel(float* __restrict__ out)
{
    __shared__ float sh[256];
    const int tid = threadIdx.x;
    const float EPS_G = 1e-6f, EPS_L = 1e-5f;

    float sa = 0.f, sb = 0.f;
    for (int i = tid; i < N_PTS; i += 256) {
        sa += logf(g_rdot[i] / (g_rowsum[i] + EPS_G));
        sb += logf(g_cdot[i] / (g_colsum[i] + EPS_G));
    }
    sa = block_reduce_256(sa, sh);
    sb = block_reduce_256(sb, sh);
    float global_loss = 0.5f * (-sa / (float)N_PTS) + 0.5f * (-sb / (float)N_PTS);

    float l0 = 0.f, l1 = 0.f, inn = 0.f;
    if (tid < G_GRP) {
        int g = tid;
        float gs = g_bsim[g * G_GRP + g];
        float rsum = 0.f, csum = 0.f;
        for (int h = 0; h < G_GRP; h++) {
            rsum += g_bsim[g * G_GRP + h];
            csum += g_bsim[h * G_GRP + g];
        }
        float neg1 = rsum - gs;
        float neg0 = csum - gs;
        float p = g_psg[g];
        l0  = logf(p / (neg0 + EPS_L));
        l1  = logf(p / (neg1 + EPS_L));
        inn = logf(p / (gs - p + EPS_L));
    }
    l0  = block_reduce_256(l0,  sh);
    l1  = block_reduce_256(l1,  sh);
    inn = block_reduce_256(inn, sh);

    if (tid == 0) {
        float loss0 = l0 / (float)G_GRP;
        float loss1 = l1 / (float)G_GRP;
        float inter = 0.5f * (loss0 + loss1);
        float inner = -(inn / (float)G_GRP);
        out[0] = global_loss + inter + inner;   // ALPHA = BETA = 1
    }
}

// ---------------------------------------------------------------------------
extern "C" void kernel_launch(void* const* d_in, const int* in_sizes, int n_in,
                              void* d_out, int out_size)
{
    const float* za   = (const float*)d_in[0];
    const float* zb   = (const float*)d_in[1];
    const float* pos  = (const float*)d_in[2];
    const int*   batch = (const int*)d_in[3];
    const float* W1 = (const float*)d_in[4];
    const float* b1 = (const float*)d_in[5];
    const float* a1 = (const float*)d_in[6];
    const float* g1 = (const float*)d_in[7];
    const float* be1 = (const float*)d_in[8];
    const float* W2 = (const float*)d_in[9];
    const float* b2 = (const float*)d_in[10];
    const float* a2 = (const float*)d_in[11];
    const float* g2 = (const float*)d_in[12];
    const float* be2 = (const float*)d_in[13];
    const float* W3 = (const float*)d_in[14];
    const float* b3 = (const float*)d_in[15];
    float* out = (float*)d_out;

    float* B0 = nullptr; float* B1 = nullptr;
    cudaGetSymbolAddress((void**)&B0, g_B0);
    cudaGetSymbolAddress((void**)&B1, g_B1);

    // Unconditional (idempotent, capture-safe; no static guards allowed)
    cudaFuncSetAttribute(sim_mma_kernel,
                         cudaFuncAttributeMaxDynamicSharedMemorySize,
                         SIM_SMEM_TOTAL);

    init_kernel<<<64, 256>>>();

    // MLP layer 1: [za; zb] @ W1 -> DyT -> B0
    gemm_dyt_kernel<<<dim3(4, 128), 256>>>(za, zb, W1, b1, a1, g1, be1, B0, H_DIM, H_DIM);
    // MLP layer 2: B0 @ W2 -> DyT -> B1
    gemm_dyt_kernel<<<dim3(4, 128), 256>>>(B0, nullptr, W2, b2, a2, g2, be2, B1, H_DIM, H_DIM);
    // MLP layer 3 + SiLU + norms + fp32 out + bf16 shadow
    gemm3_silu_kernel<<<dim3(2, 128), 256>>>(B1, W3, b3, out);

    invnorm_kernel<<<(M_TOT + 255) / 256, 256>>>();

    // Fused similarity (bf16 mma.sync) + all contrast reductions
    sim_mma_kernel<<<dim3(64, 64), 256, SIM_SMEM_TOTAL>>>(pos, batch);

    finalize_kernel<<<1, 256>>>(out);
}

// round 15
// speedup vs baseline: 2.4181x; 1.4805x over previous
#include <cuda_runtime.h>
#include <cuda_bf16.h>
#include <math.h>
#include <stdint.h>

// Problem constants
#define N_PTS   8192
#define H_DIM   512
#define D_DIM   256
#define G_GRP   64
#define M_TOT   16384   // za and zb stacked

// Device scratch (allocation-free rule: static __device__ arrays)
__device__ __nv_bfloat16 g_Xh [M_TOT * H_DIM];   // split of [za;zb]
__device__ __nv_bfloat16 g_Xl [M_TOT * H_DIM];
__device__ __nv_bfloat16 g_B0h[M_TOT * H_DIM];   // layer-1 output (DyT), split
__device__ __nv_bfloat16 g_B0l[M_TOT * H_DIM];
__device__ __nv_bfloat16 g_B1h[M_TOT * H_DIM];   // layer-2 output (DyT), split
__device__ __nv_bfloat16 g_B1l[M_TOT * H_DIM];
__device__ __nv_bfloat16 g_W1h[H_DIM * H_DIM];   // W transposed [N][K], split
__device__ __nv_bfloat16 g_W1l[H_DIM * H_DIM];
__device__ __nv_bfloat16 g_W2h[H_DIM * H_DIM];
__device__ __nv_bfloat16 g_W2l[H_DIM * H_DIM];
__device__ __nv_bfloat16 g_W3h[H_DIM * D_DIM];
__device__ __nv_bfloat16 g_W3l[H_DIM * D_DIM];
__device__ __nv_bfloat16 g_Pbf[M_TOT * D_DIM];   // bf16 shadow of projections
__device__ float g_norm2[M_TOT];
__device__ float g_invn [M_TOT];
__device__ float g_rowsum[N_PTS];
__device__ float g_colsum[N_PTS];
__device__ float g_rdot  [N_PTS];
__device__ float g_cdot  [N_PTS];
__device__ float g_psg [G_GRP];
__device__ float g_bsim[G_GRP * G_GRP];

// ---------------------------------------------------------------------------
// Helpers (sm_103 base target ONLY — no arch-suffix-gated features)
// ---------------------------------------------------------------------------
__device__ __forceinline__ uint32_t smem_u32(const void* p) {
    uint32_t a;
    asm("{ .reg .u64 t; cvta.to.shared.u64 t, %1; cvt.u32.u64 %0, t; }"
        : "=r"(a) : "l"(p));
    return a;
}

__device__ __forceinline__ void ldsm_x4(uint32_t* r, uint32_t addr) {
    asm volatile("ldmatrix.sync.aligned.m8n8.x4.shared.b16 {%0,%1,%2,%3}, [%4];"
                 : "=r"(r[0]), "=r"(r[1]), "=r"(r[2]), "=r"(r[3]) : "r"(addr));
}

__device__ __forceinline__ void mma_bf16(float* d, const uint32_t* a, const uint32_t* b) {
    asm volatile(
        "mma.sync.aligned.m16n8k16.row.col.f32.bf16.bf16.f32 "
        "{%0,%1,%2,%3}, {%4,%5,%6,%7}, {%8,%9}, {%0,%1,%2,%3};"
        : "+f"(d[0]), "+f"(d[1]), "+f"(d[2]), "+f"(d[3])
        : "r"(a[0]), "r"(a[1]), "r"(a[2]), "r"(a[3]), "r"(b[0]), "r"(b[1]));
}

__device__ __forceinline__ void split_bf16(float x, __nv_bfloat16& h, __nv_bfloat16& l) {
    h = __float2bfloat16(x);
    l = __float2bfloat16(x - __bfloat162float(h));
}

// ---------------------------------------------------------------------------
__global__ void init_kernel() {
    int i = blockIdx.x * blockDim.x + threadIdx.x;
    int stride = gridDim.x * blockDim.x;
    for (int j = i; j < M_TOT; j += stride) g_norm2[j] = 0.f;
    for (int j = i; j < N_PTS; j += stride) {
        g_rowsum[j] = 0.f; g_colsum[j] = 0.f; g_rdot[j] = 0.f; g_cdot[j] = 0.f;
    }
    for (int j = i; j < G_GRP * G_GRP; j += stride) g_bsim[j] = 0.f;
    for (int j = i; j < G_GRP; j += stride) g_psg[j] = 0.f;
}

// ---------------------------------------------------------------------------
// Split [za;zb] fp32 -> g_Xh/g_Xl bf16 (4 elems per thread)
__global__ __launch_bounds__(256)
void split_z_kernel(const float* __restrict__ za, const float* __restrict__ zb) {
    size_t base = ((size_t)blockIdx.x * 256 + threadIdx.x) * 4;
    if (base >= (size_t)M_TOT * H_DIM) return;
    int row = (int)(base >> 9);
    int k   = (int)(base & 511);
    const float* src = (row < N_PTS) ? (za + (size_t)row * 512 + k)
                                     : (zb + (size_t)(row - N_PTS) * 512 + k);
    float4 v = *(const float4*)src;
    __nv_bfloat16 h[4], l[4];
    split_bf16(v.x, h[0], l[0]); split_bf16(v.y, h[1], l[1]);
    split_bf16(v.z, h[2], l[2]); split_bf16(v.w, h[3], l[3]);
    *(uint2*)&g_Xh[base] = *(uint2*)h;
    *(uint2*)&g_Xl[base] = *(uint2*)l;
}

// Transpose + split W [K x N] fp32 row-major -> Wt [N x K] bf16 hi/lo
__global__ __launch_bounds__(256)
void tsplit_w_kernel(const float* __restrict__ W, int K, int N,
                     __nv_bfloat16* __restrict__ Oh, __nv_bfloat16* __restrict__ Ol) {
    int idx = blockIdx.x * 256 + threadIdx.x;
    if (idx >= N * K) return;
    int n = idx / K, k = idx - n * K;
    float x = W[(size_t)k * N + n];
    __nv_bfloat16 h, l;
    split_bf16(x, h, l);
    Oh[idx] = h; Ol[idx] = l;
}

// ---------------------------------------------------------------------------
// Split-bf16 MMA GEMM + DyT epilogue. 256 threads, tile 128x128, K=512.
// A (act) and Wt both K-major bf16 hi/lo. d += Ah*Wh + Ah*Wl + Al*Wh.
// smem: 4 buffers of [128 rows x 64 bf16], row stride 144B (9x16B, gcd(9,8)=1).
#define MK_ROW_B   144
#define MK_BUF     18432            // 128*144
#define MLP_SMEM   73728            // 4 buffers

__global__ __launch_bounds__(256)
void mma_dyt_kernel(const __nv_bfloat16* __restrict__ Ahg, const __nv_bfloat16* __restrict__ Alg,
                    const __nv_bfloat16* __restrict__ Wth, const __nv_bfloat16* __restrict__ Wtl,
                    const float* __restrict__ bias, const float* __restrict__ alpha,
                    const float* __restrict__ gam,  const float* __restrict__ bet,
                    __nv_bfloat16* __restrict__ Oh, __nv_bfloat16* __restrict__ Ol)
{
    extern __shared__ __align__(16) char smem[];
    const uint32_t sb = smem_u32(smem);
    const int tid = threadIdx.x, lane = tid & 31, warp = tid >> 5;
    const int rg = warp >> 1, cg = warp & 1;
    const int rowBase = blockIdx.y * 128, colBase = blockIdx.x * 128;
    const int K = H_DIM;

    float d[2][8][4];
    #pragma unroll
    for (int mt = 0; mt < 2; mt++)
        #pragma unroll
        for (int nt = 0; nt < 8; nt++)
            #pragma unroll
            for (int q = 0; q < 4; q++) d[mt][nt][q] = 0.f;

    const uint32_t aB = sb + (uint32_t)(rg * 32 + (lane & 15)) * MK_ROW_B + ((lane >> 4) * 16);
    const uint32_t bB = sb + 2 * MK_BUF
        + (uint32_t)(cg * 64 + ((lane >> 4) << 3) + (lane & 7)) * MK_ROW_B
        + (((lane >> 3) & 1) * 16);

    for (int kc = 0; kc < 8; kc++) {
        const int k0 = kc * 64;
        #pragma unroll
        for (int i = tid; i < 1024; i += 256) {
            int r = i >> 3, c = i & 7;
            *(uint4*)(smem + 0 * MK_BUF + r * MK_ROW_B + c * 16) =
                *(const uint4*)&Ahg[(size_t)(rowBase + r) * K + k0 + c * 8];
            *(uint4*)(smem + 1 * MK_BUF + r * MK_ROW_B + c * 16) =
                *(const uint4*)&Alg[(size_t)(rowBase + r) * K + k0 + c * 8];
            *(uint4*)(smem + 2 * MK_BUF + r * MK_ROW_B + c * 16) =
                *(const uint4*)&Wth[(size_t)(colBase + r) * K + k0 + c * 8];
            *(uint4*)(smem + 3 * MK_BUF + r * MK_ROW_B + c * 16) =
                *(const uint4*)&Wtl[(size_t)(colBase + r) * K + k0 + c * 8];
        }
        __syncthreads();
        #pragma unroll
        for (int s = 0; s < 4; s++) {
            const uint32_t koff = (uint32_t)s * 32;
            uint32_t ah[2][4], al[2][4];
            ldsm_x4(ah[0], aB + koff);
            ldsm_x4(ah[1], aB + 16 * MK_ROW_B + koff);
            ldsm_x4(al[0], aB + MK_BUF + koff);
            ldsm_x4(al[1], aB + MK_BUF + 16 * MK_ROW_B + koff);
            uint32_t bh[8][2], bl[8][2];
            #pragma unroll
            for (int np = 0; np < 4; np++) {
                uint32_t t[4];
                ldsm_x4(t, bB + (uint32_t)np * 16 * MK_ROW_B + koff);
                bh[2*np][0]=t[0]; bh[2*np][1]=t[1]; bh[2*np+1][0]=t[2]; bh[2*np+1][1]=t[3];
                ldsm_x4(t, bB + MK_BUF + (uint32_t)np * 16 * MK_ROW_B + koff);
                bl[2*np][0]=t[0]; bl[2*np][1]=t[1]; bl[2*np+1][0]=t[2]; bl[2*np+1][1]=t[3];
            }
            #pragma unroll
            for (int mt = 0; mt < 2; mt++)
                #pragma unroll
                for (int nt = 0; nt < 8; nt++) {
                    mma_bf16(d[mt][nt], ah[mt], bh[nt]);
                    mma_bf16(d[mt][nt], ah[mt], bl[nt]);
                    mma_bf16(d[mt][nt], al[mt], bh[nt]);
                }
        }
        __syncthreads();
    }

    // DyT epilogue; split output to hi/lo bf16 (fragment layout r1/r2, c0/c0+1)
    const float a = alpha[0];
    const int gid = lane >> 2, qp = lane & 3;
    #pragma unroll
    for (int nt = 0; nt < 8; nt++) {
        const int c0 = colBase + cg * 64 + nt * 8 + qp * 2;
        const float bb0 = bias[c0], bb1 = bias[c0 + 1];
        const float g0 = gam[c0],  g1 = gam[c0 + 1];
        const float e0 = bet[c0],  e1 = bet[c0 + 1];
        #pragma unroll
        for (int mt = 0; mt < 2; mt++) {
            const int r1 = rowBase + rg * 32 + mt * 16 + gid;
            const int r2 = r1 + 8;
            float y0 = tanhf(a * (d[mt][nt][0] + bb0)) * g0 + e0;
            float y1 = tanhf(a * (d[mt][nt][1] + bb1)) * g1 + e1;
            float y2 = tanhf(a * (d[mt][nt][2] + bb0)) * g0 + e0;
            float y3 = tanhf(a * (d[mt][nt][3] + bb1)) * g1 + e1;
            __nv_bfloat16 h0, l0, h1, l1, h2, l2, h3, l3;
            split_bf16(y0, h0, l0); split_bf16(y1, h1, l1);
            split_bf16(y2, h2, l2); split_bf16(y3, h3, l3);
            __nv_bfloat162 ph1; ph1.x = h0; ph1.y = h1;
            __nv_bfloat162 pl1; pl1.x = l0; pl1.y = l1;
            __nv_bfloat162 ph2; ph2.x = h2; ph2.y = h3;
            __nv_bfloat162 pl2; pl2.x = l2; pl2.y = l3;
            *(__nv_bfloat162*)&Oh[(size_t)r1 * 512 + c0] = ph1;
            *(__nv_bfloat162*)&Ol[(size_t)r1 * 512 + c0] = pl1;
            *(__nv_bfloat162*)&Oh[(size_t)r2 * 512 + c0] = ph2;
            *(__nv_bfloat162*)&Ol[(size_t)r2 * 512 + c0] = pl2;
        }
    }
}

// ---------------------------------------------------------------------------
// Layer 3: split-bf16 MMA + SiLU + norms + d_out fp32 + Pbf shadow. N=256.
__global__ __launch_bounds__(256)
void mma_g3_kernel(const __nv_bfloat16* __restrict__ Ahg, const __nv_bfloat16* __restrict__ Alg,
                   const __nv_bfloat16* __restrict__ Wth, const __nv_bfloat16* __restrict__ Wtl,
                   const float* __restrict__ bias, float* __restrict__ out)
{
    extern __shared__ __align__(16) char smem[];
    const uint32_t sb = smem_u32(smem);
    const int tid = threadIdx.x, lane = tid & 31, warp = tid >> 5;
    const int rg = warp >> 1, cg = warp & 1;
    const int rowBase = blockIdx.y * 128, colBase = blockIdx.x * 128;
    const int K = H_DIM;

    float d[2][8][4];
    #pragma unroll
    for (int mt = 0; mt < 2; mt++)
        #pragma unroll
        for (int nt = 0; nt < 8; nt++)
            #pragma unroll
            for (int q = 0; q < 4; q++) d[mt][nt][q] = 0.f;

    const uint32_t aB = sb + (uint32_t)(rg * 32 + (lane & 15)) * MK_ROW_B + ((lane >> 4) * 16);
    const uint32_t bB = sb + 2 * MK_BUF
        + (uint32_t)(cg * 64 + ((lane >> 4) << 3) + (lane & 7)) * MK_ROW_B
        + (((lane >> 3) & 1) * 16);

    for (int kc = 0; kc < 8; kc++) {
        const int k0 = kc * 64;
        #pragma unroll
        for (int i = tid; i < 1024; i += 256) {
            int r = i >> 3, c = i & 7;
            *(uint4*)(smem + 0 * MK_BUF + r * MK_ROW_B + c * 16) =
                *(const uint4*)&Ahg[(size_t)(rowBase + r) * K + k0 + c * 8];
            *(uint4*)(smem + 1 * MK_BUF + r * MK_ROW_B + c * 16) =
                *(const uint4*)&Alg[(size_t)(rowBase + r) * K + k0 + c * 8];
            *(uint4*)(smem + 2 * MK_BUF + r * MK_ROW_B + c * 16) =
                *(const uint4*)&Wth[(size_t)(colBase + r) * K + k0 + c * 8];
            *(uint4*)(smem + 3 * MK_BUF + r * MK_ROW_B + c * 16) =
                *(const uint4*)&Wtl[(size_t)(colBase + r) * K + k0 + c * 8];
        }
        __syncthreads();
        #pragma unroll
        for (int s = 0; s < 4; s++) {
            const uint32_t koff = (uint32_t)s * 32;
            uint32_t ah[2][4], al[2][4];
            ldsm_x4(ah[0], aB + koff);
            ldsm_x4(ah[1], aB + 16 * MK_ROW_B + koff);
            ldsm_x4(al[0], aB + MK_BUF + koff);
            ldsm_x4(al[1], aB + MK_BUF + 16 * MK_ROW_B + koff);
            uint32_t bh[8][2], bl[8][2];
            #pragma unroll
            for (int np = 0; np < 4; np++) {
                uint32_t t[4];
                ldsm_x4(t, bB + (uint32_t)np * 16 * MK_ROW_B + koff);
                bh[2*np][0]=t[0]; bh[2*np][1]=t[1]; bh[2*np+1][0]=t[2]; bh[2*np+1][1]=t[3];
                ldsm_x4(t, bB + MK_BUF + (uint32_t)np * 16 * MK_ROW_B + koff);
                bl[2*np][0]=t[0]; bl[2*np][1]=t[1]; bl[2*np+1][0]=t[2]; bl[2*np+1][1]=t[3];
            }
            #pragma unroll
            for (int mt = 0; mt < 2; mt++)
                #pragma unroll
                for (int nt = 0; nt < 8; nt++) {
                    mma_bf16(d[mt][nt], ah[mt], bh[nt]);
                    mma_bf16(d[mt][nt], ah[mt], bl[nt]);
                    mma_bf16(d[mt][nt], al[mt], bh[nt]);
                }
        }
        __syncthreads();
    }

    // SiLU epilogue + norms + fp32 out (+1 misaligned => scalar) + Pbf shadow
    const int gid = lane >> 2, qp = lane & 3;
    #pragma unroll
    for (int mt = 0; mt < 2; mt++) {
        const int r1 = rowBase + rg * 32 + mt * 16 + gid;
        const int r2 = r1 + 8;
        float n1 = 0.f, n2 = 0.f;
        #pragma unroll
        for (int nt = 0; nt < 8; nt++) {
            const int c0 = colBase + cg * 64 + nt * 8 + qp * 2;
            const float bb0 = bias[c0], bb1 = bias[c0 + 1];
            float p0 = d[mt][nt][0] + bb0, p1 = d[mt][nt][1] + bb1;
            float p2 = d[mt][nt][2] + bb0, p3 = d[mt][nt][3] + bb1;
            float v0 = p0 / (1.f + __expf(-p0));
            float v1 = p1 / (1.f + __expf(-p1));
            float v2 = p2 / (1.f + __expf(-p2));
            float v3 = p3 / (1.f + __expf(-p3));
            n1 += v0 * v0 + v1 * v1;
            n2 += v2 * v2 + v3 * v3;
            // bf16 shadow (col pair contiguous, 4B aligned)
            __nv_bfloat162 s1 = __floats2bfloat162_rn(v0, v1);
            __nv_bfloat162 s2 = __floats2bfloat162_rn(v2, v3);
            *(__nv_bfloat162*)&g_Pbf[(size_t)r1 * D_DIM + c0] = s1;
            *(__nv_bfloat162*)&g_Pbf[(size_t)r2 * D_DIM + c0] = s2;
            // d_out scalar stores
            size_t o1 = (r1 < N_PTS) ? ((size_t)r1 * 512 + c0)
                                     : ((size_t)(r1 - N_PTS) * 512 + c0 + D_DIM);
            size_t o2 = (r2 < N_PTS) ? ((size_t)r2 * 512 + c0)
                                     : ((size_t)(r2 - N_PTS) * 512 + c0 + D_DIM);
            out[1 + o1] = v0; out[2 + o1] = v1;
            out[1 + o2] = v2; out[2 + o2] = v3;
        }
        // quad reduce over qp (lane bits 0-1), then one atomic per row
        n1 += __shfl_xor_sync(0xffffffffu, n1, 1);
        n1 += __shfl_xor_sync(0xffffffffu, n1, 2);
        n2 += __shfl_xor_sync(0xffffffffu, n2, 1);
        n2 += __shfl_xor_sync(0xffffffffu, n2, 2);
        if (qp == 0) {
            atomicAdd(&g_norm2[r1], n1);
            atomicAdd(&g_norm2[r2], n2);
        }
    }
}

// ---------------------------------------------------------------------------
__global__ void invnorm_kernel() {
    int i = blockIdx.x * blockDim.x + threadIdx.x;
    if (i < M_TOT) g_invn[i] = rsqrtf(g_norm2[i]);
}

// ---------------------------------------------------------------------------
// mma.sync (bf16 HMMA) similarity GEMM + fused reductions — UNCHANGED (validated R11).
#define A_ROW_B   528
#define SM_A      0
#define SM_B      67584
#define MS_STRIDE 131
#define EP_INVB   33792
#define EP_CS     33920
#define EP_CD     34176
#define EP_RED    34432
#define SIM_SMEM_TOTAL 138752

__global__ __launch_bounds__(256)
void sim_mma_kernel(const float* __restrict__ pos, const int* __restrict__ batch)
{
    extern __shared__ __align__(16) char smem[];
    const uint32_t sb = smem_u32(smem);
    const int tid  = threadIdx.x;
    const int lane = tid & 31;
    const int warp = tid >> 5;
    const int rg = warp >> 1;
    const int cg = warp & 1;
    const int bi = blockIdx.y, bj = blockIdx.x;
    const int I0 = bi * 128, J0 = bj * 128;

    const __nv_bfloat16* Abf = g_Pbf + (size_t)I0 * D_DIM;
    const __nv_bfloat16* Bbf = g_Pbf + (size_t)(N_PTS + J0) * D_DIM;
    #pragma unroll
    for (int c = tid; c < 4096; c += 256) {
        int row = c >> 5;
        int kc  = c & 31;
        *(uint4*)(smem + SM_A + row * A_ROW_B + kc * 16) =
            *(const uint4*)&Abf[(size_t)row * D_DIM + kc * 8];
        *(uint4*)(smem + SM_B + row * A_ROW_B + kc * 16) =
            *(const uint4*)&Bbf[(size_t)row * D_DIM + kc * 8];
    }
    __syncthreads();

    float d[2][8][4];
    #pragma unroll
    for (int mt = 0; mt < 2; mt++)
        #pragma unroll
        for (int nt = 0; nt < 8; nt++)
            #pragma unroll
            for (int q = 0; q < 4; q++) d[mt][nt][q] = 0.f;

    const uint32_t aBase = sb + SM_A
        + (uint32_t)(rg * 32 + (lane & 15)) * A_ROW_B + ((lane >> 4) * 16);
    const uint32_t bBase = sb + SM_B
        + (uint32_t)(cg * 64 + ((lane >> 4) << 3) + (lane & 7)) * A_ROW_B
        + (((lane >> 3) & 1) * 16);

    #pragma unroll 4
    for (int ks = 0; ks < 16; ks++) {
        const uint32_t koff = (uint32_t)ks * 32;
        uint32_t a[2][4];
        ldsm_x4(a[0], aBase + koff);
        ldsm_x4(a[1], aBase + 16 * A_ROW_B + koff);
        uint32_t b[8][2];
        #pragma unroll
        for (int np = 0; np < 4; np++) {
            uint32_t t[4];
            ldsm_x4(t, bBase + (uint32_t)np * 16 * A_ROW_B + koff);
            b[2 * np][0] = t[0]; b[2 * np][1] = t[1];
            b[2 * np + 1][0] = t[2]; b[2 * np + 1][1] = t[3];
        }
        #pragma unroll
        for (int mt = 0; mt < 2; mt++)
            #pragma unroll
            for (int nt = 0; nt < 8; nt++)
                mma_bf16(d[mt][nt], a[mt], b[nt]);
    }
    __syncthreads();

    float* ms = (float*)smem;
    {
        const int gid = lane >> 2, qp = lane & 3;
        #pragma unroll
        for (int mt = 0; mt < 2; mt++) {
            int r1 = rg * 32 + mt * 16 + gid;
            int r2 = r1 + 8;
            #pragma unroll
            for (int nt = 0; nt < 8; nt++) {
                int c0 = cg * 64 + nt * 8 + qp * 2;
                ms[c0 * MS_STRIDE + r1]       = d[mt][nt][0];
                ms[(c0 + 1) * MS_STRIDE + r1] = d[mt][nt][1];
                ms[c0 * MS_STRIDE + r2]       = d[mt][nt][2];
                ms[(c0 + 1) * MS_STRIDE + r2] = d[mt][nt][3];
            }
        }
    }
    float* ep = (float*)smem;
    if (tid < 128) ep[EP_INVB + tid] = g_invn[N_PTS + J0 + tid];
    __syncthreads();

    const int half = tid >> 7;
    const int row  = tid & 127;
    const float inA = g_invn[I0 + row];
    const bool isdiag = (bi == bj);
    float rs = 0.f, rd = 0.f, dsum = 0.f;

    #pragma unroll 1
    for (int ci = 0; ci < 2; ci++) {
        const int cb = half * 2 + ci;

        const float* prow = pos + (size_t)(I0 + row) * N_PTS + J0 + cb * 32;
        #pragma unroll
        for (int k = 0; k < 32; k += 4) {
            float4 pv = *(const float4*)&prow[k];
            #pragma unroll
            for (int kk = 0; kk < 4; kk++) {
                int k2 = k + kk;
                int col = cb * 32 + k2;
                float dot = ms[col * MS_STRIDE + row];
                float mm = __expf(dot * inA * ep[EP_INVB + col] * 2.0f);
                ms[col * MS_STRIDE + row] = mm;
                rs += mm;
                rd += mm * ((const float*)&pv)[kk];
                if (isdiag && col == row) dsum += mm;
            }
        }
        __syncthreads();

        {
            int k = row & 31, q = row >> 5;
            int col = cb * 32 + k;
            float csp = 0.f, cdp = 0.f;
            const float* pcol = pos + (size_t)(J0 + col) * N_PTS + I0 + q * 32;
            #pragma unroll
            for (int r = 0; r < 32; r += 4) {
                float4 pv = *(const float4*)&pcol[r];
                #pragma unroll
                for (int rr = 0; rr < 4; rr++) {
                    float mmv = ms[col * MS_STRIDE + q * 32 + r + rr];
                    csp += mmv;
                    cdp += mmv * ((const float*)&pv)[rr];
                }
            }
            ep[EP_CS + half * 128 + q * 32 + k] = csp;
            ep[EP_CD + half * 128 + q * 32 + k] = cdp;
        }
        __syncthreads();
        if (row < 32) {
            float cs = ep[EP_CS + half * 128 + row] + ep[EP_CS + half * 128 + 32 + row]
                     + ep[EP_CS + half * 128 + 64 + row] + ep[EP_CS + half * 128 + 96 + row];
            float cd = ep[EP_CD + half * 128 + row] + ep[EP_CD + half * 128 + 32 + row]
                     + ep[EP_CD + half * 128 + 64 + row] + ep[EP_CD + half * 128 + 96 + row];
            atomicAdd(&g_colsum[J0 + cb * 32 + row], cs);
            atomicAdd(&g_cdot  [J0 + cb * 32 + row], cd);
        }
        __syncthreads();
    }

    atomicAdd(&g_rowsum[I0 + row], rs);
    atomicAdd(&g_rdot  [I0 + row], rd);

    const int gI = batch[I0];
    const int gJ = batch[J0];

    ep[EP_RED + tid] = rs;
    __syncthreads();
    if (tid < 32) {
        float s = 0.f;
        #pragma unroll
        for (int t = 0; t < 8; t++) s += ep[EP_RED + t * 32 + tid];
        #pragma unroll
        for (int o = 16; o > 0; o >>= 1) s += __shfl_down_sync(0xffffffffu, s, o);
        if (tid == 0) atomicAdd(&g_bsim[gI * G_GRP + gJ], s);
    }

    if (isdiag) {
        __syncthreads();
        ep[EP_RED + tid] = dsum;
        __syncthreads();
        if (tid < 32) {
            float s = 0.f;
            #pragma unroll
            for (int t = 0; t < 8; t++) s += ep[EP_RED + t * 32 + tid];
            #pragma unroll
            for (int o = 16; o > 0; o >>= 1) s += __shfl_down_sync(0xffffffffu, s, o);
            if (tid == 0) atomicAdd(&g_psg[gI], s);
        }
    }
}

// ---------------------------------------------------------------------------
__device__ __forceinline__ float block_reduce_256(float v, float* sh) {
    int tid = threadIdx.x;
    sh[tid] = v;
    __syncthreads();
    for (int s = 128; s > 0; s >>= 1) {
        if (tid < s) sh[tid] += sh[tid + s];
        __syncthreads();
    }
    float r = sh[0];
    __syncthreads();
    return r;
}

__global__ __launch_bounds__(256)
void finalize_kernel(float* __restrict__ out)
{
    __shared__ float sh[256];
    const int tid = threadIdx.x;
    const float EPS_G = 1e-6f, EPS_L = 1e-5f;

    float sa = 0.f, sb = 0.f;
    for (int i = tid; i < N_PTS; i += 256) {
        sa += logf(g_rdot[i] / (g_rowsum[i] + EPS_G));
        sb += logf(g_cdot[i] / (g_colsum[i] + EPS_G));
    }
    sa = block_reduce_256(sa, sh);
    sb = block_reduce_256(sb, sh);
    float global_loss = 0.5f * (-sa / (float)N_PTS) + 0.5f * (-sb / (float)N_PTS);

    float l0 = 0.f, l1 = 0.f, inn = 0.f;
    if (tid < G_GRP) {
        int g = tid;
        float gs = g_bsim[g * G_GRP + g];
        float rsum = 0.f, csum = 0.f;
        for (int h = 0; h < G_GRP; h++) {
            rsum += g_bsim[g * G_GRP + h];
            csum += g_bsim[h * G_GRP + g];
        }
        float neg1 = rsum - gs;
        float neg0 = csum - gs;
        float p = g_psg[g];
        l0  = logf(p / (neg0 + EPS_L));
        l1  = logf(p / (neg1 + EPS_L));
        inn = logf(p / (gs - p + EPS_L));
    }
    l0  = block_reduce_256(l0,  sh);
    l1  = block_reduce_256(l1,  sh);
    inn = block_reduce_256(inn, sh);

    if (tid == 0) {
        float loss0 = l0 / (float)G_GRP;
        float loss1 = l1 / (float)G_GRP;
        float inter = 0.5f * (loss0 + loss1);
        float inner = -(inn / (float)G_GRP);
        out[0] = global_loss + inter + inner;   // ALPHA = BETA = 1
    }
}

// ---------------------------------------------------------------------------
extern "C" void kernel_launch(void* const* d_in, const int* in_sizes, int n_in,
                              void* d_out, int out_size)
{
    const float* za   = (const float*)d_in[0];
    const float* zb   = (const float*)d_in[1];
    const float* pos  = (const float*)d_in[2];
    const int*   batch = (const int*)d_in[3];
    const float* W1 = (const float*)d_in[4];
    const float* b1 = (const float*)d_in[5];
    const float* a1 = (const float*)d_in[6];
    const float* g1 = (const float*)d_in[7];
    const float* be1 = (const float*)d_in[8];
    const float* W2 = (const float*)d_in[9];
    const float* b2 = (const float*)d_in[10];
    const float* a2 = (const float*)d_in[11];
    const float* g2 = (const float*)d_in[12];
    const float* be2 = (const float*)d_in[13];
    const float* W3 = (const float*)d_in[14];
    const float* b3 = (const float*)d_in[15];
    float* out = (float*)d_out;

    __nv_bfloat16 *Xh, *Xl, *B0h, *B0l, *B1h, *B1l;
    __nv_bfloat16 *W1h, *W1l, *W2h, *W2l, *W3h, *W3l;
    cudaGetSymbolAddress((void**)&Xh,  g_Xh);  cudaGetSymbolAddress((void**)&Xl,  g_Xl);
    cudaGetSymbolAddress((void**)&B0h, g_B0h); cudaGetSymbolAddress((void**)&B0l, g_B0l);
    cudaGetSymbolAddress((void**)&B1h, g_B1h); cudaGetSymbolAddress((void**)&B1l, g_B1l);
    cudaGetSymbolAddress((void**)&W1h, g_W1h); cudaGetSymbolAddress((void**)&W1l, g_W1l);
    cudaGetSymbolAddress((void**)&W2h, g_W2h); cudaGetSymbolAddress((void**)&W2l, g_W2l);
    cudaGetSymbolAddress((void**)&W3h, g_W3h); cudaGetSymbolAddress((void**)&W3l, g_W3l);

    // Unconditional (idempotent, capture-safe; no static guards allowed)
    cudaFuncSetAttribute(sim_mma_kernel,
                         cudaFuncAttributeMaxDynamicSharedMemorySize, SIM_SMEM_TOTAL);
    cudaFuncSetAttribute(mma_dyt_kernel,
                         cudaFuncAttributeMaxDynamicSharedMemorySize, MLP_SMEM);
    cudaFuncSetAttribute(mma_g3_kernel,
                         cudaFuncAttributeMaxDynamicSharedMemorySize, MLP_SMEM);

    init_kernel<<<64, 256>>>();

    // Split inputs/weights to bf16 hi/lo (weights transposed to [N][K])
    split_z_kernel<<<(M_TOT * H_DIM / 4 + 255) / 256, 256>>>(za, zb);
    tsplit_w_kernel<<<(H_DIM * H_DIM + 255) / 256, 256>>>(W1, H_DIM, H_DIM, W1h, W1l);
    tsplit_w_kernel<<<(H_DIM * H_DIM + 255) / 256, 256>>>(W2, H_DIM, H_DIM, W2h, W2l);
    tsplit_w_kernel<<<(H_DIM * D_DIM + 255) / 256, 256>>>(W3, H_DIM, D_DIM, W3h, W3l);

    // MLP on tensor pipe (split-bf16, 3 MMAs per product)
    mma_dyt_kernel<<<dim3(4, 128), 256, MLP_SMEM>>>(Xh,  Xl,  W1h, W1l, b1, a1, g1, be1, B0h, B0l);
    mma_dyt_kernel<<<dim3(4, 128), 256, MLP_SMEM>>>(B0h, B0l, W2h, W2l, b2, a2, g2, be2, B1h, B1l);
    mma_g3_kernel <<<dim3(2, 128), 256, MLP_SMEM>>>(B1h, B1l, W3h, W3l, b3, out);

    invnorm_kernel<<<(M_TOT + 255) / 256, 256>>>();

    // Fused similarity (bf16 mma.sync) + all contrast reductions
    sim_mma_kernel<<<dim3(64, 64), 256, SIM_SMEM_TOTAL>>>(pos, batch);

    finalize_kernel<<<1, 256>>>(out);
}